// round 9
// baseline (speedup 1.0000x reference)
#include <cuda_runtime.h>
#include <cuda_bf16.h>
#include <cuda_fp8.h>
#include <math.h>
#include <stdint.h>

// TContrastive: projections bf16 mma.sync; similarity GEMMs fp8(e4m3) mma.sync
// m16n8k32, 128x256 tiles, cp.async 2-stage, XOR-swizzled 64B-row smem.

#define NS 8192
#define DD 1024
#define STAGE_B 24576             // A 8KB + B 16KB per stage
#define RSB 2048                  // bf16 global row stride bytes

typedef __nv_bfloat16 bf16;
typedef __nv_bfloat162 bf162;

__device__ bf16 b_A1[NS*DD];
__device__ bf16 b_A2[NS*DD];
__device__ bf16 b_U1[NS*DD];
__device__ bf16 b_U2[NS*DD];
__device__ bf16 b_H1[NS*DD];
__device__ bf16 b_H2[NS*DD];
__device__ bf16 b_W1[DD*DD];
__device__ bf16 b_W2[DD*DD];
__device__ bf16 b_W3[DD*DD];
__device__ bf16 b_W4[DD*DD];
__device__ unsigned char f_F1[NS*DD];   // e4m3, normalized h * 8
__device__ unsigned char f_F2[NS*DD];
__device__ float g_r11[NS], g_r22[NS], g_r12[NS], g_c12[NS];
__device__ float g_d11[NS], g_d22[NS], g_d12[NS];
__device__ float g_loss[2];

// ---------------- primitives -------------------------------------------------
__device__ __forceinline__ void ldm_x4(uint32_t& r0, uint32_t& r1, uint32_t& r2,
                                       uint32_t& r3, uint32_t a)
{
    asm volatile("ldmatrix.sync.aligned.m8n8.x4.shared.b16 {%0,%1,%2,%3}, [%4];"
                 : "=r"(r0), "=r"(r1), "=r"(r2), "=r"(r3) : "r"(a));
}
__device__ __forceinline__ void mma_bf16(float* c, const uint32_t* a, const uint32_t* b)
{
    asm volatile("mma.sync.aligned.m16n8k16.row.col.f32.bf16.bf16.f32 "
                 "{%0,%1,%2,%3}, {%4,%5,%6,%7}, {%8,%9}, {%0,%1,%2,%3};"
                 : "+f"(c[0]), "+f"(c[1]), "+f"(c[2]), "+f"(c[3])
                 : "r"(a[0]), "r"(a[1]), "r"(a[2]), "r"(a[3]), "r"(b[0]), "r"(b[1]));
}
__device__ __forceinline__ void mma_f8(float* c, const uint32_t* a, const uint32_t* b)
{
    asm volatile("mma.sync.aligned.m16n8k32.row.col.f32.e4m3.e4m3.f32 "
                 "{%0,%1,%2,%3}, {%4,%5,%6,%7}, {%8,%9}, {%0,%1,%2,%3};"
                 : "+f"(c[0]), "+f"(c[1]), "+f"(c[2]), "+f"(c[3])
                 : "r"(a[0]), "r"(a[1]), "r"(a[2]), "r"(a[3]), "r"(b[0]), "r"(b[1]));
}
__device__ __forceinline__ void cpa16(uint32_t dst, const void* src)
{ asm volatile("cp.async.cg.shared.global [%0], [%1], 16;" :: "r"(dst), "l"(src)); }
#define CP_COMMIT() asm volatile("cp.async.commit_group;" ::: "memory")
#define CP_WAIT1()  asm volatile("cp.async.wait_group 1;" ::: "memory")
#define CP_WAIT0()  asm volatile("cp.async.wait_group 0;" ::: "memory")
__device__ __forceinline__ uint32_t swz(int row, int q)
{ return (uint32_t)(row * 64 + ((q ^ ((row >> 1) & 3)) << 4)); }

// ---------------- bf16 mainloop: 128x256 tile, K=1024, K-chunk 32 -----------
__device__ __forceinline__ void loop_bf16(const bf16* __restrict__ A,
    const bf16* __restrict__ B, int m0, int n0, char* sm, float acc[4][8][4])
{
    const int tid = threadIdx.x, lane = tid & 31, wid = tid >> 5;
    const int wm = wid >> 2, wn = wid & 3;
    const int r = lane & 7, tsel = lane >> 3;
    const int a_row = ((tsel & 1) << 3) + r, a_col = (tsel >> 1) << 3;
    const int b_row = ((tsel >> 1) << 3) + r, b_col = (tsel & 1) << 3;

    const int r0 = tid >> 2, q = tid & 3;
    const char* pA = (const char*)(A + (size_t)(m0 + r0) * DD) + q * 16;
    const char* pB = (const char*)(B + (size_t)(n0 + r0) * DD) + q * 16;
    const uint32_t smb = (uint32_t)__cvta_generic_to_shared(sm);
    const uint32_t dA = smb + swz(r0, q);
    const uint32_t dB = smb + 8192u + swz(r0, q);

    #pragma unroll
    for (int i = 0; i < 4; i++)
        #pragma unroll
        for (int j = 0; j < 8; j++)
            #pragma unroll
            for (int p = 0; p < 4; p++) acc[i][j][p] = 0.f;

    cpa16(dA, pA);                   cpa16(dA + 4096, pA + 64*RSB);
    cpa16(dB, pB);                   cpa16(dB + 4096, pB + 64*RSB);
    cpa16(dB + 8192, pB + 128*RSB);  cpa16(dB + 12288, pB + 192*RSB);
    CP_COMMIT();

    for (int c = 0; c < 32; c++) {
        if (c + 1 < 32) {
            uint32_t od = (uint32_t)((c + 1) & 1) * STAGE_B;
            const size_t og = (size_t)(c + 1) * 64;
            cpa16(dA + od, pA + og);                  cpa16(dA + od + 4096, pA + og + 64*RSB);
            cpa16(dB + od, pB + og);                  cpa16(dB + od + 4096, pB + og + 64*RSB);
            cpa16(dB + od + 8192, pB + og + 128*RSB); cpa16(dB + od + 12288, pB + og + 192*RSB);
            CP_COMMIT(); CP_WAIT1();
        } else CP_WAIT0();
        __syncthreads();

        const uint32_t sA = smb + (uint32_t)(c & 1) * STAGE_B;
        const uint32_t sB = sA + 8192u;
        #pragma unroll
        for (int ks = 0; ks < 32; ks += 16) {
            uint32_t a[4][4], b[8][2];
            #pragma unroll
            for (int ti = 0; ti < 4; ti++)
                ldm_x4(a[ti][0], a[ti][1], a[ti][2], a[ti][3],
                       sA + swz(wm*64 + ti*16 + a_row, (ks + a_col) >> 3));
            #pragma unroll
            for (int pp = 0; pp < 4; pp++)
                ldm_x4(b[2*pp][0], b[2*pp][1], b[2*pp+1][0], b[2*pp+1][1],
                       sB + swz(wn*64 + pp*16 + b_row, (ks + b_col) >> 3));
            #pragma unroll
            for (int ti = 0; ti < 4; ti++)
                #pragma unroll
                for (int tj = 0; tj < 8; tj++) mma_bf16(acc[ti][tj], a[ti], b[tj]);
        }
        __syncthreads();
    }
}

// ---------------- fp8 mainloop: 128x256 tile, K=1024 bytes, chunk 64B -------
// Same smem geometry; a kstep = k32 fp8 = 16 b16-units; ks in {0,16} b16-units.
__device__ __forceinline__ void loop_f8(const unsigned char* __restrict__ A,
    const unsigned char* __restrict__ B, int m0, int n0, char* sm, float acc[4][8][4])
{
    const int tid = threadIdx.x, lane = tid & 31, wid = tid >> 5;
    const int wm = wid >> 2, wn = wid & 3;
    const int r = lane & 7, tsel = lane >> 3;
    const int a_row = ((tsel & 1) << 3) + r, a_col = (tsel >> 1) << 3;
    const int b_row = ((tsel >> 1) << 3) + r, b_col = (tsel & 1) << 3;

    const int r0 = tid >> 2, q = tid & 3;
    const char* pA = (const char*)(A + (size_t)(m0 + r0) * DD) + q * 16;
    const char* pB = (const char*)(B + (size_t)(n0 + r0) * DD) + q * 16;
    const uint32_t smb = (uint32_t)__cvta_generic_to_shared(sm);
    const uint32_t dA = smb + swz(r0, q);
    const uint32_t dB = smb + 8192u + swz(r0, q);

    #pragma unroll
    for (int i = 0; i < 4; i++)
        #pragma unroll
        for (int j = 0; j < 8; j++)
            #pragma unroll
            for (int p = 0; p < 4; p++) acc[i][j][p] = 0.f;

    cpa16(dA, pA);                    cpa16(dA + 4096, pA + 64*DD);
    cpa16(dB, pB);                    cpa16(dB + 4096, pB + 64*DD);
    cpa16(dB + 8192, pB + 128*DD);    cpa16(dB + 12288, pB + 192*DD);
    CP_COMMIT();

    for (int c = 0; c < 16; c++) {
        if (c + 1 < 16) {
            uint32_t od = (uint32_t)((c + 1) & 1) * STAGE_B;
            const size_t og = (size_t)(c + 1) * 64;
            cpa16(dA + od, pA + og);                 cpa16(dA + od + 4096, pA + og + 64*DD);
            cpa16(dB + od, pB + og);                 cpa16(dB + od + 4096, pB + og + 64*DD);
            cpa16(dB + od + 8192, pB + og + 128*DD); cpa16(dB + od + 12288, pB + og + 192*DD);
            CP_COMMIT(); CP_WAIT1();
        } else CP_WAIT0();
        __syncthreads();

        const uint32_t sA = smb + (uint32_t)(c & 1) * STAGE_B;
        const uint32_t sB = sA + 8192u;
        #pragma unroll
        for (int ks = 0; ks < 32; ks += 16) {
            uint32_t a[4][4], b[8][2];
            #pragma unroll
            for (int ti = 0; ti < 4; ti++)
                ldm_x4(a[ti][0], a[ti][1], a[ti][2], a[ti][3],
                       sA + swz(wm*64 + ti*16 + a_row, (ks + a_col) >> 3));
            #pragma unroll
            for (int pp = 0; pp < 4; pp++)
                ldm_x4(b[2*pp][0], b[2*pp][1], b[2*pp+1][0], b[2*pp+1][1],
                       sB + swz(wn*64 + pp*16 + b_row, (ks + b_col) >> 3));
            #pragma unroll
            for (int ti = 0; ti < 4; ti++)
                #pragma unroll
                for (int tj = 0; tj < 8; tj++) mma_f8(acc[ti][tj], a[ti], b[tj]);
        }
        __syncthreads();
    }
}

// ---------------- projection GEMM (bf16) ------------------------------------
template<int MODE>
__device__ __forceinline__ void gemm_body(const bf16* __restrict__ A,
    const bf16* __restrict__ W, const float* __restrict__ bias, bf16* __restrict__ C)
{
    __shared__ __align__(16) char sm[2 * STAGE_B];
    const int m0 = blockIdx.y * 128, n0 = blockIdx.x * 256;
    const int lane = threadIdx.x & 31, wid = threadIdx.x >> 5;
    const int wm = wid >> 2, wn = wid & 3;
    const int grp = lane >> 2, qid = lane & 3;

    float acc[4][8][4];
    loop_bf16(A, W, m0, n0, sm, acc);

    #pragma unroll
    for (int tj = 0; tj < 8; tj++) {
        int gc = n0 + wn*64 + tj*8 + qid*2;
        float bv0 = bias[gc], bv1 = bias[gc+1];
        #pragma unroll
        for (int ti = 0; ti < 4; ti++)
            #pragma unroll
            for (int h = 0; h < 2; h++) {
                int gr = m0 + wm*64 + ti*16 + h*8 + grp;
                float v0 = acc[ti][tj][h*2+0] + bv0;
                float v1 = acc[ti][tj][h*2+1] + bv1;
                if (MODE == 1) {
                    v0 = v0 > 0.f ? v0 : expm1f(v0);
                    v1 = v1 > 0.f ? v1 : expm1f(v1);
                }
                *(bf162*)(C + (size_t)gr * DD + gc) = __floats2bfloat162_rn(v0, v1);
            }
    }
}

__global__ __launch_bounds__(256) void g_A1W1U1(const float* b) { gemm_body<1>(b_A1, b_W1, b, b_U1); }
__global__ __launch_bounds__(256) void g_A2W1U2(const float* b) { gemm_body<1>(b_A2, b_W1, b, b_U2); }
__global__ __launch_bounds__(256) void g_U1W2H1(const float* b) { gemm_body<0>(b_U1, b_W2, b, b_H1); }
__global__ __launch_bounds__(256) void g_U2W2H2(const float* b) { gemm_body<0>(b_U2, b_W2, b, b_H2); }
__global__ __launch_bounds__(256) void g_A1W3U1(const float* b) { gemm_body<1>(b_A1, b_W3, b, b_U1); }
__global__ __launch_bounds__(256) void g_A2W3U2(const float* b) { gemm_body<1>(b_A2, b_W3, b, b_U2); }
__global__ __launch_bounds__(256) void g_U1W4H1(const float* b) { gemm_body<0>(b_U1, b_W4, b, b_H1); }
__global__ __launch_bounds__(256) void g_U2W4H2(const float* b) { gemm_body<0>(b_U2, b_W4, b, b_H2); }

// ---------------- fused fp8 exp-similarity + reductions ---------------------
// acc holds dot(h_i*8, h_j*8) -> sim/tau = 2*acc/64 = acc*0.03125.
template<bool SYM>
__device__ __forceinline__ void sim_body(const unsigned char* __restrict__ A,
    const unsigned char* __restrict__ B, float* __restrict__ rs, float* __restrict__ cs,
    float* __restrict__ dg)
{
    const int bi = blockIdx.y;
    const int bj2 = SYM ? (bi / 2 + blockIdx.x) : blockIdx.x;
    if (SYM && bj2 >= 32) return;

    __shared__ __align__(16) char sm[2 * STAGE_B];
    const int m0 = bi * 128, n0 = bj2 * 256;
    const int lane = threadIdx.x & 31, wid = threadIdx.x >> 5;
    const int wm = wid >> 2, wn = wid & 3;
    const int grp = lane >> 2, qid = lane & 3;

    float acc[4][8][4];
    loop_f8(A, B, m0, n0, sm, acc);

    const int chalf = 2*bj2 + (wn >> 1);
    if (SYM && chalf < bi) return;
    const bool diag = (chalf == bi);
    const bool doCols = (!SYM) || (chalf > bi);
    float* csOut = SYM ? rs : cs;

    #pragma unroll
    for (int ti = 0; ti < 4; ti++)
        #pragma unroll
        for (int h = 0; h < 2; h++) {
            int gr = m0 + wm*64 + ti*16 + h*8 + grp;
            float rsum = 0.f;
            #pragma unroll
            for (int tj = 0; tj < 8; tj++) {
                int gc = n0 + wn*64 + tj*8 + qid*2;
                float e0 = __expf(0.03125f * acc[ti][tj][h*2+0]);
                float e1 = __expf(0.03125f * acc[ti][tj][h*2+1]);
                acc[ti][tj][h*2+0] = e0;
                acc[ti][tj][h*2+1] = e1;
                rsum += e0 + e1;
                if (diag) {
                    if (gr == gc)     dg[gr] = e0;
                    if (gr == gc + 1) dg[gr] = e1;
                }
            }
            rsum += __shfl_down_sync(0xffffffffu, rsum, 2, 4);
            rsum += __shfl_down_sync(0xffffffffu, rsum, 1, 4);
            if (qid == 0) atomicAdd(&rs[gr], rsum);
        }

    if (doCols) {
        #pragma unroll
        for (int tj = 0; tj < 8; tj++) {
            float c0 = 0.f, c1 = 0.f;
            #pragma unroll
            for (int ti = 0; ti < 4; ti++) {
                c0 += acc[ti][tj][0] + acc[ti][tj][2];
                c1 += acc[ti][tj][1] + acc[ti][tj][3];
            }
            #pragma unroll
            for (int o = 4; o <= 16; o <<= 1) {
                c0 += __shfl_xor_sync(0xffffffffu, c0, o);
                c1 += __shfl_xor_sync(0xffffffffu, c1, o);
            }
            if (grp == 0) {
                int gc = n0 + wn*64 + tj*8 + qid*2;
                atomicAdd(&csOut[gc],   c0);
                atomicAdd(&csOut[gc+1], c1);
            }
        }
    }
}

__global__ __launch_bounds__(256) void sim_F1_sym() { sim_body<true >(f_F1, f_F1, g_r11, nullptr, g_d11); }
__global__ __launch_bounds__(256) void sim_F2_sym() { sim_body<true >(f_F2, f_F2, g_r22, nullptr, g_d22); }
__global__ __launch_bounds__(256) void sim_F_full() { sim_body<false>(f_F1, f_F2, g_r12, g_c12, g_d12); }

// ---------------- aux kernels ------------------------------------------------
__device__ __forceinline__ void conv_body(const float* __restrict__ s,
                                          bf16* __restrict__ d, int n4)
{
    int i = blockIdx.x * blockDim.x + threadIdx.x;
    if (i < n4) {
        float4 v = ((const float4*)s)[i];
        ((bf162*)d)[i*2+0] = __floats2bfloat162_rn(v.x, v.y);
        ((bf162*)d)[i*2+1] = __floats2bfloat162_rn(v.z, v.w);
    }
}
__global__ void conv_A1(const float* s) { conv_body(s, b_A1, NS*DD/4); }
__global__ void conv_A2(const float* s) { conv_body(s, b_A2, NS*DD/4); }
__global__ void conv_W1(const float* s) { conv_body(s, b_W1, DD*DD/4); }
__global__ void conv_W2(const float* s) { conv_body(s, b_W2, DD*DD/4); }
__global__ void conv_W3(const float* s) { conv_body(s, b_W3, DD*DD/4); }
__global__ void conv_W4(const float* s) { conv_body(s, b_W4, DD*DD/4); }

__device__ __forceinline__ void trans_body(const float* __restrict__ in,
                                           bf16* __restrict__ out)
{
    __shared__ float t[32][33];
    const float* s = in  + (size_t)blockIdx.x * 1024;
    bf16*        d = out + (size_t)blockIdx.x * 1024;
    for (int i = threadIdx.x; i < 1024; i += 256) t[i >> 5][i & 31] = s[i];
    __syncthreads();
    for (int i = threadIdx.x; i < 1024; i += 256)
        d[i] = __float2bfloat16(t[i & 31][i >> 5]);
}
__global__ __launch_bounds__(256) void trans_A1(const float* in) { trans_body(in, b_A1); }
__global__ __launch_bounds__(256) void trans_A2(const float* in) { trans_body(in, b_A2); }

// normalize bf16 row, write e4m3 scaled by 8
__device__ __forceinline__ void norm_body(const bf16* __restrict__ H,
                                          unsigned char* __restrict__ F)
{
    int row = blockIdx.x;
    const uint2* p = (const uint2*)(H + (size_t)row * DD) + threadIdx.x;
    uint2 raw = *p;
    bf162 v0 = *(bf162*)&raw.x;
    bf162 v1 = *(bf162*)&raw.y;
    float a = __bfloat162float(v0.x), b = __bfloat162float(v0.y);
    float c = __bfloat162float(v1.x), d = __bfloat162float(v1.y);
    float s = a*a + b*b + c*c + d*d;
    #pragma unroll
    for (int o = 16; o; o >>= 1) s += __shfl_xor_sync(0xffffffffu, s, o);
    __shared__ float red[8];
    int lane = threadIdx.x & 31, w = threadIdx.x >> 5;
    if (lane == 0) red[w] = s;
    __syncthreads();
    __shared__ float invn;
    if (threadIdx.x == 0) {
        float t = 0.f;
        #pragma unroll
        for (int i = 0; i < 8; i++) t += red[i];
        invn = rsqrtf(t);
    }
    __syncthreads();
    float iv = invn * 8.f;
    uint32_t pk = (uint32_t)__nv_cvt_float_to_fp8(a*iv, __NV_SATFINITE, __NV_E4M3)
        | ((uint32_t)__nv_cvt_float_to_fp8(b*iv, __NV_SATFINITE, __NV_E4M3) << 8)
        | ((uint32_t)__nv_cvt_float_to_fp8(c*iv, __NV_SATFINITE, __NV_E4M3) << 16)
        | ((uint32_t)__nv_cvt_float_to_fp8(d*iv, __NV_SATFINITE, __NV_E4M3) << 24);
    ((uint32_t*)(F + (size_t)row * DD))[threadIdx.x] = pk;
}
__global__ __launch_bounds__(256) void norm_H1() { norm_body(b_H1, f_F1); }
__global__ __launch_bounds__(256) void norm_H2() { norm_body(b_H2, f_F2); }

__global__ void zero_stats(int zl)
{
    int i = blockIdx.x * blockDim.x + threadIdx.x;
    if (i < NS) { g_r11[i] = 0.f; g_r22[i] = 0.f; g_r12[i] = 0.f; g_c12[i] = 0.f; }
    if (zl && i < 2) g_loss[i] = 0.f;
}

__global__ void loss_reduce(int slot)
{
    int i = blockIdx.x * blockDim.x + threadIdx.x;
    float v = 0.f;
    if (i < NS) {
        float ld = logf(g_d12[i]);
        float l1 = logf(g_r11[i] + g_r12[i] - g_d11[i]) - ld;
        float l2 = logf(g_r22[i] + g_c12[i] - g_d22[i]) - ld;
        v = 0.5f * (l1 + l2) * (1.0f / NS);
    }
    #pragma unroll
    for (int o = 16; o; o >>= 1) v += __shfl_down_sync(0xffffffffu, v, o);
    if ((threadIdx.x & 31) == 0) atomicAdd(&g_loss[slot], v);
}

__global__ void finalize_k(const float* __restrict__ w_r1, float* __restrict__ out)
{
    float w = fminf(fmaxf(w_r1[0], 0.f), 1.f);
    out[0] = w * g_loss[0] + (1.f - w) * g_loss[1];
}

// ----------------------------------------------------------------------------
extern "C" void kernel_launch(void* const* d_in, const int* in_sizes, int n_in,
                              void* d_out, int out_size)
{
    const float* ta   = (const float*)d_in[0];
    const float* tb   = (const float*)d_in[1];
    const float* W1   = (const float*)d_in[2];
    const float* b1   = (const float*)d_in[3];
    const float* W2   = (const float*)d_in[4];
    const float* b2   = (const float*)d_in[5];
    const float* W3   = (const float*)d_in[6];
    const float* b3   = (const float*)d_in[7];
    const float* W4   = (const float*)d_in[8];
    const float* b4   = (const float*)d_in[9];
    const float* w_r1 = (const float*)d_in[10];
    float* out = (float*)d_out;

    dim3 gProj(DD / 256, NS / 128);
    dim3 gSim(32, 64);
    int  zb  = (NS + 255) / 256;
    int  cbA = (NS*DD/4 + 255) / 256;
    int  cbW = (DD*DD/4 + 255) / 256;

    conv_W1<<<cbW, 256>>>(W1);
    conv_W2<<<cbW, 256>>>(W2);
    conv_W3<<<cbW, 256>>>(W3);
    conv_W4<<<cbW, 256>>>(W4);
    zero_stats<<<zb, 256>>>(1);

    conv_A1<<<cbA, 256>>>(ta);
    conv_A2<<<cbA, 256>>>(tb);
    g_A1W1U1<<<gProj, 256>>>(b1);
    g_A2W1U2<<<gProj, 256>>>(b1);
    g_U1W2H1<<<gProj, 256>>>(b2);
    g_U2W2H2<<<gProj, 256>>>(b2);
    norm_H1<<<NS, 256>>>();
    norm_H2<<<NS, 256>>>();
    sim_F1_sym<<<gSim, 256>>>();
    sim_F2_sym<<<gSim, 256>>>();
    sim_F_full<<<gSim, 256>>>();
    loss_reduce<<<zb, 256>>>(0);

    trans_A1<<<NS, 256>>>(ta);
    trans_A2<<<NS, 256>>>(tb);
    zero_stats<<<zb, 256>>>(0);
    g_A1W3U1<<<gProj, 256>>>(b3);
    g_A2W3U2<<<gProj, 256>>>(b3);
    g_U1W4H1<<<gProj, 256>>>(b4);
    g_U2W4H2<<<gProj, 256>>>(b4);
    norm_H1<<<NS, 256>>>();
    norm_H2<<<NS, 256>>>();
    sim_F1_sym<<<gSim, 256>>>();
    sim_F2_sym<<<gSim, 256>>>();
    sim_F_full<<<gSim, 256>>>();
    loss_reduce<<<zb, 256>>>(1);

    finalize_k<<<1, 1>>>(w_r1, out);
}

// round 10
// speedup vs baseline: 1.1381x; 1.1381x over previous
#include <cuda_runtime.h>
#include <cuda_bf16.h>
#include <math.h>
#include <stdint.h>

// TContrastive: bf16 mma.sync, 128x256 tiles, cp.async 2-stage,
// single-barrier-per-chunk mainloop, XOR-swizzled 64B-row smem.

#define NS 8192
#define DD 1024
#define STAGE_B 24576             // A 8KB + B 16KB per stage
#define RSB 2048                  // bf16 global row stride bytes

typedef __nv_bfloat16 bf16;
typedef __nv_bfloat162 bf162;

__device__ bf16 b_A1[NS*DD];
__device__ bf16 b_A2[NS*DD];
__device__ bf16 b_U1[NS*DD];
__device__ bf16 b_U2[NS*DD];
__device__ bf16 b_H1[NS*DD];
__device__ bf16 b_H2[NS*DD];
__device__ bf16 b_W1[DD*DD];
__device__ bf16 b_W2[DD*DD];
__device__ bf16 b_W3[DD*DD];
__device__ bf16 b_W4[DD*DD];
__device__ float g_r11[NS], g_r22[NS], g_r12[NS], g_c12[NS];
__device__ float g_d11[NS], g_d22[NS], g_d12[NS];
__device__ float g_loss[2];

// ---------------- primitives -------------------------------------------------
__device__ __forceinline__ void ldm_x4(uint32_t& r0, uint32_t& r1, uint32_t& r2,
                                       uint32_t& r3, uint32_t a)
{
    asm volatile("ldmatrix.sync.aligned.m8n8.x4.shared.b16 {%0,%1,%2,%3}, [%4];"
                 : "=r"(r0), "=r"(r1), "=r"(r2), "=r"(r3) : "r"(a));
}
__device__ __forceinline__ void mma16816(float* c, const uint32_t* a, const uint32_t* b)
{
    asm volatile("mma.sync.aligned.m16n8k16.row.col.f32.bf16.bf16.f32 "
                 "{%0,%1,%2,%3}, {%4,%5,%6,%7}, {%8,%9}, {%0,%1,%2,%3};"
                 : "+f"(c[0]), "+f"(c[1]), "+f"(c[2]), "+f"(c[3])
                 : "r"(a[0]), "r"(a[1]), "r"(a[2]), "r"(a[3]), "r"(b[0]), "r"(b[1]));
}
__device__ __forceinline__ void cpa16(uint32_t dst, const void* src)
{ asm volatile("cp.async.cg.shared.global [%0], [%1], 16;" :: "r"(dst), "l"(src)); }
#define CP_COMMIT() asm volatile("cp.async.commit_group;" ::: "memory")
#define CP_WAIT0()  asm volatile("cp.async.wait_group 0;" ::: "memory")
__device__ __forceinline__ uint32_t swz(int row, int q)
{ return (uint32_t)(row * 64 + ((q ^ ((row >> 1) & 3)) << 4)); }

// ---------------- mainloop: 128x256 fp32 tile of A·B^T, K=1024 --------------
// Warp grid 2x4 (wm,wn); warp tile 64x64; acc[ti][tj][4].
// Per chunk: WAIT0 -> sync -> issue c+1 copies (other stage) -> compute c.
__device__ __forceinline__ void mma_mainloop(const bf16* __restrict__ A,
    const bf16* __restrict__ B, int m0, int n0, char* sm, float acc[4][8][4])
{
    const int tid = threadIdx.x, lane = tid & 31, wid = tid >> 5;
    const int wm = wid >> 2, wn = wid & 3;
    const int r = lane & 7, tsel = lane >> 3;
    const int a_row = ((tsel & 1) << 3) + r, a_col = (tsel >> 1) << 3;
    const int b_row = ((tsel >> 1) << 3) + r, b_col = (tsel & 1) << 3;

    const int r0 = tid >> 2, q = tid & 3;
    const char* pA = (const char*)(A + (size_t)(m0 + r0) * DD) + q * 16;
    const char* pB = (const char*)(B + (size_t)(n0 + r0) * DD) + q * 16;
    const uint32_t smb = (uint32_t)__cvta_generic_to_shared(sm);
    const uint32_t dA = smb + swz(r0, q);
    const uint32_t dB = smb + 8192u + swz(r0, q);

    #pragma unroll
    for (int i = 0; i < 4; i++)
        #pragma unroll
        for (int j = 0; j < 8; j++)
            #pragma unroll
            for (int p = 0; p < 4; p++) acc[i][j][p] = 0.f;

    // chunk 0 -> stage 0
    cpa16(dA, pA);                   cpa16(dA + 4096, pA + 64*RSB);
    cpa16(dB, pB);                   cpa16(dB + 4096, pB + 64*RSB);
    cpa16(dB + 8192, pB + 128*RSB);  cpa16(dB + 12288, pB + 192*RSB);
    CP_COMMIT();

    for (int c = 0; c < 32; c++) {
        CP_WAIT0();
        __syncthreads();
        if (c + 1 < 32) {
            uint32_t od = (uint32_t)((c + 1) & 1) * STAGE_B;
            const size_t og = (size_t)(c + 1) * 64;
            cpa16(dA + od, pA + og);                  cpa16(dA + od + 4096, pA + og + 64*RSB);
            cpa16(dB + od, pB + og);                  cpa16(dB + od + 4096, pB + og + 64*RSB);
            cpa16(dB + od + 8192, pB + og + 128*RSB); cpa16(dB + od + 12288, pB + og + 192*RSB);
            CP_COMMIT();
        }
        const uint32_t sA = smb + (uint32_t)(c & 1) * STAGE_B;
        const uint32_t sB = sA + 8192u;
        #pragma unroll
        for (int ks = 0; ks < 32; ks += 16) {
            uint32_t a[4][4], b[8][2];
            #pragma unroll
            for (int ti = 0; ti < 4; ti++)
                ldm_x4(a[ti][0], a[ti][1], a[ti][2], a[ti][3],
                       sA + swz(wm*64 + ti*16 + a_row, (ks + a_col) >> 3));
            #pragma unroll
            for (int pp = 0; pp < 4; pp++)
                ldm_x4(b[2*pp][0], b[2*pp][1], b[2*pp+1][0], b[2*pp+1][1],
                       sB + swz(wn*64 + pp*16 + b_row, (ks + b_col) >> 3));
            #pragma unroll
            for (int ti = 0; ti < 4; ti++)
                #pragma unroll
                for (int tj = 0; tj < 8; tj++)
                    mma16816(acc[ti][tj], a[ti], b[tj]);
        }
    }
}

// ---------------- projection GEMM: C = [elu](A·W^T + bias), bf16 out --------
template<int MODE>
__device__ __forceinline__ void gemm_body(const bf16* __restrict__ A,
    const bf16* __restrict__ W, const float* __restrict__ bias, bf16* __restrict__ C)
{
    __shared__ __align__(16) char sm[2 * STAGE_B];
    const int m0 = blockIdx.y * 128, n0 = blockIdx.x * 256;
    const int lane = threadIdx.x & 31, wid = threadIdx.x >> 5;
    const int wm = wid >> 2, wn = wid & 3;
    const int grp = lane >> 2, qid = lane & 3;

    float acc[4][8][4];
    mma_mainloop(A, W, m0, n0, sm, acc);

    #pragma unroll
    for (int tj = 0; tj < 8; tj++) {
        int gc = n0 + wn*64 + tj*8 + qid*2;
        float bv0 = bias[gc], bv1 = bias[gc+1];
        #pragma unroll
        for (int ti = 0; ti < 4; ti++)
            #pragma unroll
            for (int h = 0; h < 2; h++) {
                int gr = m0 + wm*64 + ti*16 + h*8 + grp;
                float v0 = acc[ti][tj][h*2+0] + bv0;
                float v1 = acc[ti][tj][h*2+1] + bv1;
                if (MODE == 1) {
                    v0 = v0 > 0.f ? v0 : expm1f(v0);
                    v1 = v1 > 0.f ? v1 : expm1f(v1);
                }
                *(bf162*)(C + (size_t)gr * DD + gc) = __floats2bfloat162_rn(v0, v1);
            }
    }
}

__global__ __launch_bounds__(256) void g_A1W1U1(const float* b) { gemm_body<1>(b_A1, b_W1, b, b_U1); }
__global__ __launch_bounds__(256) void g_A2W1U2(const float* b) { gemm_body<1>(b_A2, b_W1, b, b_U2); }
__global__ __launch_bounds__(256) void g_U1W2H1(const float* b) { gemm_body<0>(b_U1, b_W2, b, b_H1); }
__global__ __launch_bounds__(256) void g_U2W2H2(const float* b) { gemm_body<0>(b_U2, b_W2, b, b_H2); }
__global__ __launch_bounds__(256) void g_A1W3U1(const float* b) { gemm_body<1>(b_A1, b_W3, b, b_U1); }
__global__ __launch_bounds__(256) void g_A2W3U2(const float* b) { gemm_body<1>(b_A2, b_W3, b, b_U2); }
__global__ __launch_bounds__(256) void g_U1W4H1(const float* b) { gemm_body<0>(b_U1, b_W4, b, b_H1); }
__global__ __launch_bounds__(256) void g_U2W4H2(const float* b) { gemm_body<0>(b_U2, b_W4, b, b_H2); }

// ---------------- fused exp-similarity + reductions -------------------------
// 128x256 tile; each warp's 64 cols lie in one 128-col half: chalf=2*bj2+(wn>>1).
template<bool SYM>
__device__ __forceinline__ void sim_body(const bf16* __restrict__ A,
    const bf16* __restrict__ B, float* __restrict__ rs, float* __restrict__ cs,
    float* __restrict__ dg)
{
    const int bi = blockIdx.y;
    const int bj2 = SYM ? (bi / 2 + blockIdx.x) : blockIdx.x;
    if (SYM && bj2 >= 32) return;

    __shared__ __align__(16) char sm[2 * STAGE_B];
    const int m0 = bi * 128, n0 = bj2 * 256;
    const int lane = threadIdx.x & 31, wid = threadIdx.x >> 5;
    const int wm = wid >> 2, wn = wid & 3;
    const int grp = lane >> 2, qid = lane & 3;

    float acc[4][8][4];
    mma_mainloop(A, B, m0, n0, sm, acc);

    const int chalf = 2*bj2 + (wn >> 1);
    if (SYM && chalf < bi) return;          // warp-uniform
    const bool diag = (chalf == bi);
    const bool doCols = (!SYM) || (chalf > bi);
    float* csOut = SYM ? rs : cs;

    #pragma unroll
    for (int ti = 0; ti < 4; ti++)
        #pragma unroll
        for (int h = 0; h < 2; h++) {
            int gr = m0 + wm*64 + ti*16 + h*8 + grp;
            float rsum = 0.f;
            #pragma unroll
            for (int tj = 0; tj < 8; tj++) {
                int gc = n0 + wn*64 + tj*8 + qid*2;
                float e0 = __expf(2.f * acc[ti][tj][h*2+0]);
                float e1 = __expf(2.f * acc[ti][tj][h*2+1]);
                acc[ti][tj][h*2+0] = e0;
                acc[ti][tj][h*2+1] = e1;
                rsum += e0 + e1;
                if (diag) {
                    if (gr == gc)     dg[gr] = e0;
                    if (gr == gc + 1) dg[gr] = e1;
                }
            }
            rsum += __shfl_down_sync(0xffffffffu, rsum, 2, 4);
            rsum += __shfl_down_sync(0xffffffffu, rsum, 1, 4);
            if (qid == 0) atomicAdd(&rs[gr], rsum);
        }

    if (doCols) {
        #pragma unroll
        for (int tj = 0; tj < 8; tj++) {
            float c0 = 0.f, c1 = 0.f;
            #pragma unroll
            for (int ti = 0; ti < 4; ti++) {
                c0 += acc[ti][tj][0] + acc[ti][tj][2];
                c1 += acc[ti][tj][1] + acc[ti][tj][3];
            }
            #pragma unroll
            for (int o = 4; o <= 16; o <<= 1) {
                c0 += __shfl_xor_sync(0xffffffffu, c0, o);
                c1 += __shfl_xor_sync(0xffffffffu, c1, o);
            }
            if (grp == 0) {
                int gc = n0 + wn*64 + tj*8 + qid*2;
                atomicAdd(&csOut[gc],   c0);
                atomicAdd(&csOut[gc+1], c1);
            }
        }
    }
}

__global__ __launch_bounds__(256) void sim_H1_sym() { sim_body<true >(b_H1, b_H1, g_r11, nullptr, g_d11); }
__global__ __launch_bounds__(256) void sim_H2_sym() { sim_body<true >(b_H2, b_H2, g_r22, nullptr, g_d22); }
__global__ __launch_bounds__(256) void sim_H_full() { sim_body<false>(b_H1, b_H2, g_r12, g_c12, g_d12); }

// ---------------- aux kernels ------------------------------------------------
// fp32 -> bf16 with 4 independent loads in flight per thread
__device__ __forceinline__ void conv_body(const float* __restrict__ s,
                                          bf16* __restrict__ d, int n4)
{
    int i = blockIdx.x * blockDim.x + threadIdx.x;
    int st = gridDim.x * blockDim.x;          // n4/4 exactly
    float4 v0 = ((const float4*)s)[i];
    float4 v1 = ((const float4*)s)[i + st];
    float4 v2 = ((const float4*)s)[i + 2*st];
    float4 v3 = ((const float4*)s)[i + 3*st];
    ((bf162*)d)[(i)*2+0]      = __floats2bfloat162_rn(v0.x, v0.y);
    ((bf162*)d)[(i)*2+1]      = __floats2bfloat162_rn(v0.z, v0.w);
    ((bf162*)d)[(i+st)*2+0]   = __floats2bfloat162_rn(v1.x, v1.y);
    ((bf162*)d)[(i+st)*2+1]   = __floats2bfloat162_rn(v1.z, v1.w);
    ((bf162*)d)[(i+2*st)*2+0] = __floats2bfloat162_rn(v2.x, v2.y);
    ((bf162*)d)[(i+2*st)*2+1] = __floats2bfloat162_rn(v2.z, v2.w);
    ((bf162*)d)[(i+3*st)*2+0] = __floats2bfloat162_rn(v3.x, v3.y);
    ((bf162*)d)[(i+3*st)*2+1] = __floats2bfloat162_rn(v3.z, v3.w);
}
__global__ void conv_A1(const float* s) { conv_body(s, b_A1, NS*DD/4); }
__global__ void conv_A2(const float* s) { conv_body(s, b_A2, NS*DD/4); }
__global__ void conv_W1(const float* s) { conv_body(s, b_W1, DD*DD/4); }
__global__ void conv_W2(const float* s) { conv_body(s, b_W2, DD*DD/4); }
__global__ void conv_W3(const float* s) { conv_body(s, b_W3, DD*DD/4); }
__global__ void conv_W4(const float* s) { conv_body(s, b_W4, DD*DD/4); }

__device__ __forceinline__ void trans_body(const float* __restrict__ in,
                                           bf16* __restrict__ out)
{
    __shared__ float t[32][33];
    const float* s = in  + (size_t)blockIdx.x * 1024;
    bf16*        d = out + (size_t)blockIdx.x * 1024;
    for (int i = threadIdx.x; i < 1024; i += 256) t[i >> 5][i & 31] = s[i];
    __syncthreads();
    for (int i = threadIdx.x; i < 1024; i += 256)
        d[i] = __float2bfloat16(t[i & 31][i >> 5]);
}
__global__ __launch_bounds__(256) void trans_A1(const float* in) { trans_body(in, b_A1); }
__global__ __launch_bounds__(256) void trans_A2(const float* in) { trans_body(in, b_A2); }

__device__ __forceinline__ void norm_body(bf16* __restrict__ H)
{
    int row = blockIdx.x;
    uint2* p = (uint2*)(H + (size_t)row * DD) + threadIdx.x;
    uint2 raw = *p;
    bf162 v0 = *(bf162*)&raw.x;
    bf162 v1 = *(bf162*)&raw.y;
    float a = __bfloat162float(v0.x), b = __bfloat162float(v0.y);
    float c = __bfloat162float(v1.x), d = __bfloat162float(v1.y);
    float s = a*a + b*b + c*c + d*d;
    #pragma unroll
    for (int o = 16; o; o >>= 1) s += __shfl_xor_sync(0xffffffffu, s, o);
    __shared__ float red[8];
    int lane = threadIdx.x & 31, w = threadIdx.x >> 5;
    if (lane == 0) red[w] = s;
    __syncthreads();
    __shared__ float invn;
    if (threadIdx.x == 0) {
        float t = 0.f;
        #pragma unroll
        for (int i = 0; i < 8; i++) t += red[i];
        invn = rsqrtf(t);
    }
    __syncthreads();
    float iv = invn;
    uint2 ow;
    *(bf162*)&ow.x = __floats2bfloat162_rn(a*iv, b*iv);
    *(bf162*)&ow.y = __floats2bfloat162_rn(c*iv, d*iv);
    *p = ow;
}
__global__ __launch_bounds__(256) void norm_H1() { norm_body(b_H1); }
__global__ __launch_bounds__(256) void norm_H2() { norm_body(b_H2); }

__global__ void zero_stats(int zl)
{
    int i = blockIdx.x * blockDim.x + threadIdx.x;
    if (i < NS) { g_r11[i] = 0.f; g_r22[i] = 0.f; g_r12[i] = 0.f; g_c12[i] = 0.f; }
    if (zl && i < 2) g_loss[i] = 0.f;
}

__global__ void loss_reduce(int slot)
{
    int i = blockIdx.x * blockDim.x + threadIdx.x;
    float v = 0.f;
    if (i < NS) {
        float ld = logf(g_d12[i]);
        float l1 = logf(g_r11[i] + g_r12[i] - g_d11[i]) - ld;
        float l2 = logf(g_r22[i] + g_c12[i] - g_d22[i]) - ld;
        v = 0.5f * (l1 + l2) * (1.0f / NS);
    }
    #pragma unroll
    for (int o = 16; o; o >>= 1) v += __shfl_down_sync(0xffffffffu, v, o);
    if ((threadIdx.x & 31) == 0) atomicAdd(&g_loss[slot], v);
}

__global__ void finalize_k(const float* __restrict__ w_r1, float* __restrict__ out)
{
    float w = fminf(fmaxf(w_r1[0], 0.f), 1.f);
    out[0] = w * g_loss[0] + (1.f - w) * g_loss[1];
}

// ----------------------------------------------------------------------------
extern "C" void kernel_launch(void* const* d_in, const int* in_sizes, int n_in,
                              void* d_out, int out_size)
{
    const float* ta   = (const float*)d_in[0];
    const float* tb   = (const float*)d_in[1];
    const float* W1   = (const float*)d_in[2];
    const float* b1   = (const float*)d_in[3];
    const float* W2   = (const float*)d_in[4];
    const float* b2   = (const float*)d_in[5];
    const float* W3   = (const float*)d_in[6];
    const float* b3   = (const float*)d_in[7];
    const float* W4   = (const float*)d_in[8];
    const float* b4   = (const float*)d_in[9];
    const float* w_r1 = (const float*)d_in[10];
    float* out = (float*)d_out;

    dim3 gProj(DD / 256, NS / 128);
    dim3 gSim(32, 64);
    int  zb  = (NS + 255) / 256;
    int  cbA = NS*DD/4/4/256;    // 4 float4 per thread
    int  cbW = DD*DD/4/4/256;

    conv_W1<<<cbW, 256>>>(W1);
    conv_W2<<<cbW, 256>>>(W2);
    conv_W3<<<cbW, 256>>>(W3);
    conv_W4<<<cbW, 256>>>(W4);
    zero_stats<<<zb, 256>>>(1);

    conv_A1<<<cbA, 256>>>(ta);
    conv_A2<<<cbA, 256>>>(tb);
    g_A1W1U1<<<gProj, 256>>>(b1);
    g_A2W1U2<<<gProj, 256>>>(b1);
    g_U1W2H1<<<gProj, 256>>>(b2);
    g_U2W2H2<<<gProj, 256>>>(b2);
    norm_H1<<<NS, 256>>>();
    norm_H2<<<NS, 256>>>();
    sim_H1_sym<<<gSim, 256>>>();
    sim_H2_sym<<<gSim, 256>>>();
    sim_H_full<<<gSim, 256>>>();
    loss_reduce<<<zb, 256>>>(0);

    trans_A1<<<NS, 256>>>(ta);
    trans_A2<<<NS, 256>>>(tb);
    zero_stats<<<zb, 256>>>(0);
    g_A1W3U1<<<gProj, 256>>>(b3);
    g_A2W3U2<<<gProj, 256>>>(b3);
    g_U1W4H1<<<gProj, 256>>>(b4);
    g_U2W4H2<<<gProj, 256>>>(b4);
    norm_H1<<<NS, 256>>>();
    norm_H2<<<NS, 256>>>();
    sim_H1_sym<<<gSim, 256>>>();
    sim_H2_sym<<<gSim, 256>>>();
    sim_H_full<<<gSim, 256>>>();
    loss_reduce<<<zb, 256>>>(1);

    finalize_k<<<1, 1>>>(w_r1, out);
}

// round 11
// speedup vs baseline: 1.1867x; 1.0427x over previous
#include <cuda_runtime.h>
#include <cuda_bf16.h>
#include <math.h>
#include <stdint.h>

// TContrastive: bf16 mma.sync 128x256 tiles, cp.async 2-stage single-barrier
// pipeline, XOR-swizzled 64B-row smem, launch-fused phases via blockIdx.z.

#define NS 8192
#define DD 1024
#define STAGE_B 24576             // A 8KB + B 16KB per stage
#define RSB 2048                  // bf16 global row stride bytes

typedef __nv_bfloat16 bf16;
typedef __nv_bfloat162 bf162;

// row view A, col view Ac; U/H per view
__device__ bf16 b_A1[NS*DD],  b_A2[NS*DD];
__device__ bf16 b_A1c[NS*DD], b_A2c[NS*DD];
__device__ bf16 b_U1[NS*DD],  b_U2[NS*DD],  b_U1c[NS*DD], b_U2c[NS*DD];
__device__ bf16 b_H1[NS*DD],  b_H2[NS*DD],  b_H1c[NS*DD], b_H2c[NS*DD];
__device__ bf16 b_W1[DD*DD], b_W2[DD*DD], b_W3[DD*DD], b_W4[DD*DD];
__device__ float g_r11[2*NS], g_r22[2*NS], g_r12[2*NS], g_c12[2*NS];
__device__ float g_d11[2*NS], g_d22[2*NS], g_d12[2*NS];
__device__ float g_loss[2];

// ---------------- primitives -------------------------------------------------
__device__ __forceinline__ void ldm_x4(uint32_t& r0, uint32_t& r1, uint32_t& r2,
                                       uint32_t& r3, uint32_t a)
{
    asm volatile("ldmatrix.sync.aligned.m8n8.x4.shared.b16 {%0,%1,%2,%3}, [%4];"
                 : "=r"(r0), "=r"(r1), "=r"(r2), "=r"(r3) : "r"(a));
}
__device__ __forceinline__ void mma16816(float* c, const uint32_t* a, const uint32_t* b)
{
    asm volatile("mma.sync.aligned.m16n8k16.row.col.f32.bf16.bf16.f32 "
                 "{%0,%1,%2,%3}, {%4,%5,%6,%7}, {%8,%9}, {%0,%1,%2,%3};"
                 : "+f"(c[0]), "+f"(c[1]), "+f"(c[2]), "+f"(c[3])
                 : "r"(a[0]), "r"(a[1]), "r"(a[2]), "r"(a[3]), "r"(b[0]), "r"(b[1]));
}
__device__ __forceinline__ void cpa16(uint32_t dst, const void* src)
{ asm volatile("cp.async.cg.shared.global [%0], [%1], 16;" :: "r"(dst), "l"(src)); }
#define CP_COMMIT() asm volatile("cp.async.commit_group;" ::: "memory")
#define CP_WAIT0()  asm volatile("cp.async.wait_group 0;" ::: "memory")
__device__ __forceinline__ uint32_t swz(int row, int q)
{ return (uint32_t)(row * 64 + ((q ^ ((row >> 1) & 3)) << 4)); }

// ---------------- mainloop: 128x256 fp32 tile of A·B^T, K=1024 --------------
__device__ __forceinline__ void mma_mainloop(const bf16* __restrict__ A,
    const bf16* __restrict__ B, int m0, int n0, char* sm, float acc[4][8][4])
{
    const int tid = threadIdx.x, lane = tid & 31, wid = tid >> 5;
    const int wm = wid >> 2, wn = wid & 3;
    const int r = lane & 7, tsel = lane >> 3;
    const int a_row = ((tsel & 1) << 3) + r, a_col = (tsel >> 1) << 3;
    const int b_row = ((tsel >> 1) << 3) + r, b_col = (tsel & 1) << 3;

    const int r0 = tid >> 2, q = tid & 3;
    const char* pA = (const char*)(A + (size_t)(m0 + r0) * DD) + q * 16;
    const char* pB = (const char*)(B + (size_t)(n0 + r0) * DD) + q * 16;
    const uint32_t smb = (uint32_t)__cvta_generic_to_shared(sm);
    const uint32_t dA = smb + swz(r0, q);
    const uint32_t dB = smb + 8192u + swz(r0, q);

    #pragma unroll
    for (int i = 0; i < 4; i++)
        #pragma unroll
        for (int j = 0; j < 8; j++)
            #pragma unroll
            for (int p = 0; p < 4; p++) acc[i][j][p] = 0.f;

    cpa16(dA, pA);                   cpa16(dA + 4096, pA + 64*RSB);
    cpa16(dB, pB);                   cpa16(dB + 4096, pB + 64*RSB);
    cpa16(dB + 8192, pB + 128*RSB);  cpa16(dB + 12288, pB + 192*RSB);
    CP_COMMIT();

    for (int c = 0; c < 32; c++) {
        CP_WAIT0();
        __syncthreads();
        if (c + 1 < 32) {
            uint32_t od = (uint32_t)((c + 1) & 1) * STAGE_B;
            const size_t og = (size_t)(c + 1) * 64;
            cpa16(dA + od, pA + og);                  cpa16(dA + od + 4096, pA + og + 64*RSB);
            cpa16(dB + od, pB + og);                  cpa16(dB + od + 4096, pB + og + 64*RSB);
            cpa16(dB + od + 8192, pB + og + 128*RSB); cpa16(dB + od + 12288, pB + og + 192*RSB);
            CP_COMMIT();
        }
        const uint32_t sA = smb + (uint32_t)(c & 1) * STAGE_B;
        const uint32_t sB = sA + 8192u;
        #pragma unroll
        for (int ks = 0; ks < 32; ks += 16) {
            uint32_t a[4][4], b[8][2];
            #pragma unroll
            for (int ti = 0; ti < 4; ti++)
                ldm_x4(a[ti][0], a[ti][1], a[ti][2], a[ti][3],
                       sA + swz(wm*64 + ti*16 + a_row, (ks + a_col) >> 3));
            #pragma unroll
            for (int pp = 0; pp < 4; pp++)
                ldm_x4(b[2*pp][0], b[2*pp][1], b[2*pp+1][0], b[2*pp+1][1],
                       sB + swz(wn*64 + pp*16 + b_row, (ks + b_col) >> 3));
            #pragma unroll
            for (int ti = 0; ti < 4; ti++)
                #pragma unroll
                for (int tj = 0; tj < 8; tj++)
                    mma16816(acc[ti][tj], a[ti], b[tj]);
        }
    }
}

// ---------------- projection GEMM body --------------------------------------
template<int MODE>
__device__ __forceinline__ void gemm_body(const bf16* __restrict__ A,
    const bf16* __restrict__ W, const float* __restrict__ bias, bf16* __restrict__ C)
{
    __shared__ __align__(16) char sm[2 * STAGE_B];
    const int m0 = blockIdx.y * 128, n0 = blockIdx.x * 256;
    const int lane = threadIdx.x & 31, wid = threadIdx.x >> 5;
    const int wm = wid >> 2, wn = wid & 3;
    const int grp = lane >> 2, qid = lane & 3;

    float acc[4][8][4];
    mma_mainloop(A, W, m0, n0, sm, acc);

    #pragma unroll
    for (int tj = 0; tj < 8; tj++) {
        int gc = n0 + wn*64 + tj*8 + qid*2;
        float bv0 = bias[gc], bv1 = bias[gc+1];
        #pragma unroll
        for (int ti = 0; ti < 4; ti++)
            #pragma unroll
            for (int h = 0; h < 2; h++) {
                int gr = m0 + wm*64 + ti*16 + h*8 + grp;
                float v0 = acc[ti][tj][h*2+0] + bv0;
                float v1 = acc[ti][tj][h*2+1] + bv1;
                if (MODE == 1) {
                    v0 = v0 > 0.f ? v0 : expm1f(v0);
                    v1 = v1 > 0.f ? v1 : expm1f(v1);
                }
                *(bf162*)(C + (size_t)gr * DD + gc) = __floats2bfloat162_rn(v0, v1);
            }
    }
}

// z-fused projection launches (4 independent GEMMs each)
__global__ __launch_bounds__(256) void proj1_all(const float* b1, const float* b3)
{
    int z = blockIdx.z;
    const bf16 *A, *W; bf16* C;
    if (z == 0)      { A = b_A1;  W = b_W1; C = b_U1;  }
    else if (z == 1) { A = b_A2;  W = b_W1; C = b_U2;  }
    else if (z == 2) { A = b_A1c; W = b_W3; C = b_U1c; }
    else             { A = b_A2c; W = b_W3; C = b_U2c; }
    gemm_body<1>(A, W, (z < 2) ? b1 : b3, C);
}
__global__ __launch_bounds__(256) void proj2_all(const float* b2, const float* b4)
{
    int z = blockIdx.z;
    const bf16 *A, *W; bf16* C;
    if (z == 0)      { A = b_U1;  W = b_W2; C = b_H1;  }
    else if (z == 1) { A = b_U2;  W = b_W2; C = b_H2;  }
    else if (z == 2) { A = b_U1c; W = b_W4; C = b_H1c; }
    else             { A = b_U2c; W = b_W4; C = b_H2c; }
    gemm_body<0>(A, W, (z < 2) ? b2 : b4, C);
}

// ---------------- fused similarity: all 6 matrices in one launch -------------
// z = v*3 + m; m: 0=sym(h1), 1=sym(h2), 2=full. grid (32, 64, 6).
__global__ __launch_bounds__(256) void sim_all()
{
    const int z = blockIdx.z;
    const int v = z / 3, m = z % 3;
    const bool SYM = (m != 2);
    const int bi = blockIdx.y;
    const int bj2 = SYM ? (bi / 2 + blockIdx.x) : blockIdx.x;
    if (bj2 >= 32) return;

    const bf16 *A, *B;
    float *rs, *cs, *dg;
    if (v == 0) {
        A = (m == 1) ? b_H2 : b_H1;
        B = (m == 0) ? b_H1 : b_H2;
        rs = (m == 0) ? g_r11 : (m == 1) ? g_r22 : g_r12;
        dg = (m == 0) ? g_d11 : (m == 1) ? g_d22 : g_d12;
    } else {
        A = (m == 1) ? b_H2c : b_H1c;
        B = (m == 0) ? b_H1c : b_H2c;
        rs = ((m == 0) ? g_r11 : (m == 1) ? g_r22 : g_r12) + NS;
        dg = ((m == 0) ? g_d11 : (m == 1) ? g_d22 : g_d12) + NS;
    }
    cs = SYM ? rs : (g_c12 + v*NS);

    __shared__ __align__(16) char sm[2 * STAGE_B];
    const int m0 = bi * 128, n0 = bj2 * 256;
    const int lane = threadIdx.x & 31, wid = threadIdx.x >> 5;
    const int wm = wid >> 2, wn = wid & 3;
    const int grp = lane >> 2, qid = lane & 3;

    float acc[4][8][4];
    mma_mainloop(A, B, m0, n0, sm, acc);

    const int chalf = 2*bj2 + (wn >> 1);
    if (SYM && chalf < bi) return;          // warp-uniform
    const bool diag = SYM && (chalf == bi);
    const bool doCols = (!SYM) || (chalf > bi);

    #pragma unroll
    for (int ti = 0; ti < 4; ti++)
        #pragma unroll
        for (int h = 0; h < 2; h++) {
            int gr = m0 + wm*64 + ti*16 + h*8 + grp;
            float rsum = 0.f;
            #pragma unroll
            for (int tj = 0; tj < 8; tj++) {
                int gc = n0 + wn*64 + tj*8 + qid*2;
                float e0 = __expf(2.f * acc[ti][tj][h*2+0]);
                float e1 = __expf(2.f * acc[ti][tj][h*2+1]);
                acc[ti][tj][h*2+0] = e0;
                acc[ti][tj][h*2+1] = e1;
                rsum += e0 + e1;
                if (m == 2 && bj2*2 + 1 >= bi && bj2*2 <= bi) { // full diag tile half
                    if (gr == gc)     dg[gr] = e0;
                    if (gr == gc + 1) dg[gr] = e1;
                } else if (diag) {
                    if (gr == gc)     dg[gr] = e0;
                    if (gr == gc + 1) dg[gr] = e1;
                }
            }
            rsum += __shfl_down_sync(0xffffffffu, rsum, 2, 4);
            rsum += __shfl_down_sync(0xffffffffu, rsum, 1, 4);
            if (qid == 0) atomicAdd(&rs[gr], rsum);
        }

    if (doCols) {
        #pragma unroll
        for (int tj = 0; tj < 8; tj++) {
            float c0 = 0.f, c1 = 0.f;
            #pragma unroll
            for (int ti = 0; ti < 4; ti++) {
                c0 += acc[ti][tj][0] + acc[ti][tj][2];
                c1 += acc[ti][tj][1] + acc[ti][tj][3];
            }
            #pragma unroll
            for (int o = 4; o <= 16; o <<= 1) {
                c0 += __shfl_xor_sync(0xffffffffu, c0, o);
                c1 += __shfl_xor_sync(0xffffffffu, c1, o);
            }
            if (grp == 0) {
                int gc = n0 + wn*64 + tj*8 + qid*2;
                atomicAdd(&cs[gc],   c0);
                atomicAdd(&cs[gc+1], c1);
            }
        }
    }
}

// ---------------- aux kernels (z-fused) --------------------------------------
__global__ void conv_all(const float* ta, const float* tb,
                         const float* W1, const float* W2,
                         const float* W3, const float* W4)
{
    int z = blockIdx.z;
    int nblk = (z < 2) ? 2048 : 256;
    if (blockIdx.x >= (unsigned)nblk) return;
    const float* s; bf16* d;
    if (z == 0)      { s = ta; d = b_A1; }
    else if (z == 1) { s = tb; d = b_A2; }
    else if (z == 2) { s = W1; d = b_W1; }
    else if (z == 3) { s = W2; d = b_W2; }
    else if (z == 4) { s = W3; d = b_W3; }
    else             { s = W4; d = b_W4; }
    int i = blockIdx.x * blockDim.x + threadIdx.x;
    int st = nblk * 256;
    float4 v0 = ((const float4*)s)[i];
    float4 v1 = ((const float4*)s)[i + st];
    float4 v2 = ((const float4*)s)[i + 2*st];
    float4 v3 = ((const float4*)s)[i + 3*st];
    ((bf162*)d)[(i)*2+0]      = __floats2bfloat162_rn(v0.x, v0.y);
    ((bf162*)d)[(i)*2+1]      = __floats2bfloat162_rn(v0.z, v0.w);
    ((bf162*)d)[(i+st)*2+0]   = __floats2bfloat162_rn(v1.x, v1.y);
    ((bf162*)d)[(i+st)*2+1]   = __floats2bfloat162_rn(v1.z, v1.w);
    ((bf162*)d)[(i+2*st)*2+0] = __floats2bfloat162_rn(v2.x, v2.y);
    ((bf162*)d)[(i+2*st)*2+1] = __floats2bfloat162_rn(v2.z, v2.w);
    ((bf162*)d)[(i+3*st)*2+0] = __floats2bfloat162_rn(v3.x, v3.y);
    ((bf162*)d)[(i+3*st)*2+1] = __floats2bfloat162_rn(v3.z, v3.w);
}

__global__ __launch_bounds__(256) void trans_all(const float* ta, const float* tb)
{
    const float* in = blockIdx.z ? tb : ta;
    bf16* out = blockIdx.z ? b_A2c : b_A1c;
    __shared__ float t[32][33];
    const float* s = in  + (size_t)blockIdx.x * 1024;
    bf16*        d = out + (size_t)blockIdx.x * 1024;
    for (int i = threadIdx.x; i < 1024; i += 256) t[i >> 5][i & 31] = s[i];
    __syncthreads();
    for (int i = threadIdx.x; i < 1024; i += 256)
        d[i] = __float2bfloat16(t[i & 31][i >> 5]);
}

__global__ __launch_bounds__(256) void norm_all()
{
    bf16* H = (blockIdx.z == 0) ? b_H1 : (blockIdx.z == 1) ? b_H2
            : (blockIdx.z == 2) ? b_H1c : b_H2c;
    int row = blockIdx.x;
    uint2* p = (uint2*)(H + (size_t)row * DD) + threadIdx.x;
    uint2 raw = *p;
    bf162 v0 = *(bf162*)&raw.x;
    bf162 v1 = *(bf162*)&raw.y;
    float a = __bfloat162float(v0.x), b = __bfloat162float(v0.y);
    float c = __bfloat162float(v1.x), d = __bfloat162float(v1.y);
    float s = a*a + b*b + c*c + d*d;
    #pragma unroll
    for (int o = 16; o; o >>= 1) s += __shfl_xor_sync(0xffffffffu, s, o);
    __shared__ float red[8];
    int lane = threadIdx.x & 31, w = threadIdx.x >> 5;
    if (lane == 0) red[w] = s;
    __syncthreads();
    __shared__ float invn;
    if (threadIdx.x == 0) {
        float t = 0.f;
        #pragma unroll
        for (int i = 0; i < 8; i++) t += red[i];
        invn = rsqrtf(t);
    }
    __syncthreads();
    float iv = invn;
    uint2 ow;
    *(bf162*)&ow.x = __floats2bfloat162_rn(a*iv, b*iv);
    *(bf162*)&ow.y = __floats2bfloat162_rn(c*iv, d*iv);
    *p = ow;
}

__global__ void zero_stats()
{
    int i = blockIdx.x * blockDim.x + threadIdx.x;
    if (i < 2*NS) { g_r11[i] = 0.f; g_r22[i] = 0.f; g_r12[i] = 0.f; g_c12[i] = 0.f; }
    if (i < 2) g_loss[i] = 0.f;
}

__global__ void loss_all()
{
    int v = blockIdx.z;
    int i = blockIdx.x * blockDim.x + threadIdx.x;
    float val = 0.f;
    if (i < NS) {
        int k = v*NS + i;
        float ld = logf(g_d12[k]);
        float l1 = logf(g_r11[k] + g_r12[k] - g_d11[k]) - ld;
        float l2 = logf(g_r22[k] + g_c12[k] - g_d22[k]) - ld;
        val = 0.5f * (l1 + l2) * (1.0f / NS);
    }
    #pragma unroll
    for (int o = 16; o; o >>= 1) val += __shfl_down_sync(0xffffffffu, val, o);
    if ((threadIdx.x & 31) == 0) atomicAdd(&g_loss[v], val);
}

__global__ void finalize_k(const float* __restrict__ w_r1, float* __restrict__ out)
{
    float w = fminf(fmaxf(w_r1[0], 0.f), 1.f);
    out[0] = w * g_loss[0] + (1.f - w) * g_loss[1];
}

// ----------------------------------------------------------------------------
extern "C" void kernel_launch(void* const* d_in, const int* in_sizes, int n_in,
                              void* d_out, int out_size)
{
    const float* ta   = (const float*)d_in[0];
    const float* tb   = (const float*)d_in[1];
    const float* W1   = (const float*)d_in[2];
    const float* b1   = (const float*)d_in[3];
    const float* W2   = (const float*)d_in[4];
    const float* b2   = (const float*)d_in[5];
    const float* W3   = (const float*)d_in[6];
    const float* b3   = (const float*)d_in[7];
    const float* W4   = (const float*)d_in[8];
    const float* b4   = (const float*)d_in[9];
    const float* w_r1 = (const float*)d_in[10];
    float* out = (float*)d_out;

    conv_all <<<dim3(2048, 1, 6), 256>>>(ta, tb, W1, W2, W3, W4);
    trans_all<<<dim3(NS, 1, 2), 256>>>(ta, tb);
    zero_stats<<<(2*NS + 255)/256, 256>>>();
    proj1_all<<<dim3(4, 64, 4), 256>>>(b1, b3);
    proj2_all<<<dim3(4, 64, 4), 256>>>(b2, b4);
    norm_all <<<dim3(NS, 1, 4), 256>>>();
    sim_all  <<<dim3(32, 64, 6), 256>>>();
    loss_all <<<dim3(32, 1, 2), 256>>>();
    finalize_k<<<1, 1>>>(w_r1, out);
}

// round 12
// speedup vs baseline: 1.4270x; 1.2024x over previous
#include <cuda_runtime.h>
#include <cuda_bf16.h>
#include <math.h>
#include <stdint.h>

// TContrastive: bf16 mma.sync 128x128 tiles @ 2 CTAs/SM, cp.async 2-stage
// single-barrier pipeline, XOR-swizzled 64B-row smem, z-fused launches.

#define NS 8192
#define DD 1024
#define STAGE_B 16384             // A 8KB + B 8KB per stage
#define RSB 2048                  // bf16 global row stride bytes

typedef __nv_bfloat16 bf16;
typedef __nv_bfloat162 bf162;

__device__ bf16 b_A1[NS*DD],  b_A2[NS*DD];
__device__ bf16 b_A1c[NS*DD], b_A2c[NS*DD];
__device__ bf16 b_U1[NS*DD],  b_U2[NS*DD],  b_U1c[NS*DD], b_U2c[NS*DD];
__device__ bf16 b_H1[NS*DD],  b_H2[NS*DD],  b_H1c[NS*DD], b_H2c[NS*DD];
__device__ bf16 b_W1[DD*DD], b_W2[DD*DD], b_W3[DD*DD], b_W4[DD*DD];
__device__ float g_r11[2*NS], g_r22[2*NS], g_r12[2*NS], g_c12[2*NS];
__device__ float g_d11[2*NS], g_d22[2*NS], g_d12[2*NS];
__device__ float g_loss[2];

// ---------------- primitives -------------------------------------------------
__device__ __forceinline__ void ldm_x4(uint32_t& r0, uint32_t& r1, uint32_t& r2,
                                       uint32_t& r3, uint32_t a)
{
    asm volatile("ldmatrix.sync.aligned.m8n8.x4.shared.b16 {%0,%1,%2,%3}, [%4];"
                 : "=r"(r0), "=r"(r1), "=r"(r2), "=r"(r3) : "r"(a));
}
__device__ __forceinline__ void mma16816(float* c, const uint32_t* a, const uint32_t* b)
{
    asm volatile("mma.sync.aligned.m16n8k16.row.col.f32.bf16.bf16.f32 "
                 "{%0,%1,%2,%3}, {%4,%5,%6,%7}, {%8,%9}, {%0,%1,%2,%3};"
                 : "+f"(c[0]), "+f"(c[1]), "+f"(c[2]), "+f"(c[3])
                 : "r"(a[0]), "r"(a[1]), "r"(a[2]), "r"(a[3]), "r"(b[0]), "r"(b[1]));
}
__device__ __forceinline__ void cpa16(uint32_t dst, const void* src)
{ asm volatile("cp.async.cg.shared.global [%0], [%1], 16;" :: "r"(dst), "l"(src)); }
#define CP_COMMIT() asm volatile("cp.async.commit_group;" ::: "memory")
#define CP_WAIT0()  asm volatile("cp.async.wait_group 0;" ::: "memory")
__device__ __forceinline__ uint32_t swz(int row, int q)
{ return (uint32_t)(row * 64 + ((q ^ ((row >> 1) & 3)) << 4)); }

// ---------------- mainloop: 128x128 fp32 tile of A·B^T, K=1024 --------------
// Warp grid 2x4 (wm,wn); warp tile 64x32; acc[ti 0..3][tj 0..3][4].
// Per chunk: WAIT0 -> sync -> issue c+1 copies (other stage) -> compute c.
__device__ __forceinline__ void mma_mainloop(const bf16* __restrict__ A,
    const bf16* __restrict__ B, int m0, int n0, char* sm, float acc[4][4][4])
{
    const int tid = threadIdx.x, lane = tid & 31, wid = tid >> 5;
    const int wm = wid >> 2, wn = wid & 3;
    const int r = lane & 7, tsel = lane >> 3;
    const int a_row = ((tsel & 1) << 3) + r, a_col = (tsel >> 1) << 3;
    const int b_row = ((tsel >> 1) << 3) + r, b_col = (tsel & 1) << 3;

    // copy slots: ids 0..1023 -> half(A/B), row, 16B quarter (4 per thread)
    const char* src[4]; uint32_t dof[4];
    const uint32_t smb = (uint32_t)__cvta_generic_to_shared(sm);
    #pragma unroll
    for (int it = 0; it < 4; it++) {
        int id = it * 256 + tid;
        int half = id >> 9, rem = id & 511;
        int row = rem >> 2, q = rem & 3;
        src[it] = (const char*)((half ? B + (size_t)(n0 + row) * DD
                                      : A + (size_t)(m0 + row) * DD) + q * 8);
        dof[it] = smb + half * 8192u + swz(row, q);
    }

    #pragma unroll
    for (int i = 0; i < 4; i++)
        #pragma unroll
        for (int j = 0; j < 4; j++)
            #pragma unroll
            for (int p = 0; p < 4; p++) acc[i][j][p] = 0.f;

    #pragma unroll
    for (int it = 0; it < 4; it++) cpa16(dof[it], src[it]);
    CP_COMMIT();

    for (int c = 0; c < 32; c++) {
        CP_WAIT0();
        __syncthreads();
        if (c + 1 < 32) {
            uint32_t od = (uint32_t)((c + 1) & 1) * STAGE_B;
            const size_t og = (size_t)(c + 1) * 64;
            #pragma unroll
            for (int it = 0; it < 4; it++) cpa16(dof[it] + od, src[it] + og);
            CP_COMMIT();
        }
        const uint32_t sA = smb + (uint32_t)(c & 1) * STAGE_B;
        const uint32_t sB = sA + 8192u;
        #pragma unroll
        for (int ks = 0; ks < 32; ks += 16) {
            uint32_t a[4][4], b[4][2];
            #pragma unroll
            for (int ti = 0; ti < 4; ti++)
                ldm_x4(a[ti][0], a[ti][1], a[ti][2], a[ti][3],
                       sA + swz(wm*64 + ti*16 + a_row, (ks + a_col) >> 3));
            #pragma unroll
            for (int pp = 0; pp < 2; pp++)
                ldm_x4(b[2*pp][0], b[2*pp][1], b[2*pp+1][0], b[2*pp+1][1],
                       sB + swz(wn*32 + pp*16 + b_row, (ks + b_col) >> 3));
            #pragma unroll
            for (int ti = 0; ti < 4; ti++)
                #pragma unroll
                for (int tj = 0; tj < 4; tj++)
                    mma16816(acc[ti][tj], a[ti], b[tj]);
        }
    }
}

// ---------------- projection GEMM body --------------------------------------
template<int MODE>
__device__ __forceinline__ void gemm_body(const bf16* __restrict__ A,
    const bf16* __restrict__ W, const float* __restrict__ bias, bf16* __restrict__ C)
{
    __shared__ __align__(16) char sm[2 * STAGE_B];
    const int m0 = blockIdx.y * 128, n0 = blockIdx.x * 128;
    const int lane = threadIdx.x & 31, wid = threadIdx.x >> 5;
    const int wm = wid >> 2, wn = wid & 3;
    const int grp = lane >> 2, qid = lane & 3;

    float acc[4][4][4];
    mma_mainloop(A, W, m0, n0, sm, acc);

    #pragma unroll
    for (int tj = 0; tj < 4; tj++) {
        int gc = n0 + wn*32 + tj*8 + qid*2;
        float bv0 = bias[gc], bv1 = bias[gc+1];
        #pragma unroll
        for (int ti = 0; ti < 4; ti++)
            #pragma unroll
            for (int h = 0; h < 2; h++) {
                int gr = m0 + wm*64 + ti*16 + h*8 + grp;
                float v0 = acc[ti][tj][h*2+0] + bv0;
                float v1 = acc[ti][tj][h*2+1] + bv1;
                if (MODE == 1) {
                    v0 = v0 > 0.f ? v0 : expm1f(v0);
                    v1 = v1 > 0.f ? v1 : expm1f(v1);
                }
                *(bf162*)(C + (size_t)gr * DD + gc) = __floats2bfloat162_rn(v0, v1);
            }
    }
}

__global__ __launch_bounds__(256, 2) void proj1_all(const float* b1, const float* b3)
{
    int z = blockIdx.z;
    const bf16 *A, *W; bf16* C;
    if (z == 0)      { A = b_A1;  W = b_W1; C = b_U1;  }
    else if (z == 1) { A = b_A2;  W = b_W1; C = b_U2;  }
    else if (z == 2) { A = b_A1c; W = b_W3; C = b_U1c; }
    else             { A = b_A2c; W = b_W3; C = b_U2c; }
    gemm_body<1>(A, W, (z < 2) ? b1 : b3, C);
}
__global__ __launch_bounds__(256, 2) void proj2_all(const float* b2, const float* b4)
{
    int z = blockIdx.z;
    const bf16 *A, *W; bf16* C;
    if (z == 0)      { A = b_U1;  W = b_W2; C = b_H1;  }
    else if (z == 1) { A = b_U2;  W = b_W2; C = b_H2;  }
    else if (z == 2) { A = b_U1c; W = b_W4; C = b_H1c; }
    else             { A = b_U2c; W = b_W4; C = b_H2c; }
    gemm_body<0>(A, W, (z < 2) ? b2 : b4, C);
}

// ---------------- fused similarity: all 6 matrices in one launch -------------
// z = v*3 + m; m: 0=sym(h1), 1=sym(h2), 2=full. grid (64, 64, 6).
__global__ __launch_bounds__(256, 2) void sim_all()
{
    const int z = blockIdx.z;
    const int v = z / 3, m = z % 3;
    const bool SYM = (m != 2);
    const int bi = blockIdx.y;
    const int bj = SYM ? (bi + blockIdx.x) : blockIdx.x;
    if (SYM && bj >= 64) return;

    const bf16 *A, *B;
    float *rs, *cs, *dg;
    if (v == 0) {
        A = (m == 1) ? b_H2 : b_H1;
        B = (m == 0) ? b_H1 : b_H2;
        rs = (m == 0) ? g_r11 : (m == 1) ? g_r22 : g_r12;
        dg = (m == 0) ? g_d11 : (m == 1) ? g_d22 : g_d12;
    } else {
        A = (m == 1) ? b_H2c : b_H1c;
        B = (m == 0) ? b_H1c : b_H2c;
        rs = ((m == 0) ? g_r11 : (m == 1) ? g_r22 : g_r12) + NS;
        dg = ((m == 0) ? g_d11 : (m == 1) ? g_d22 : g_d12) + NS;
    }
    cs = SYM ? rs : (g_c12 + v*NS);

    __shared__ __align__(16) char sm[2 * STAGE_B];
    const int m0 = bi * 128, n0 = bj * 128;
    const int lane = threadIdx.x & 31, wid = threadIdx.x >> 5;
    const int wm = wid >> 2, wn = wid & 3;
    const int grp = lane >> 2, qid = lane & 3;
    const bool diag = (bi == bj);
    const bool doCols = (!SYM) || (bj > bi);

    float acc[4][4][4];
    mma_mainloop(A, B, m0, n0, sm, acc);

    #pragma unroll
    for (int ti = 0; ti < 4; ti++)
        #pragma unroll
        for (int h = 0; h < 2; h++) {
            int gr = m0 + wm*64 + ti*16 + h*8 + grp;
            float rsum = 0.f;
            #pragma unroll
            for (int tj = 0; tj < 4; tj++) {
                int gc = n0 + wn*32 + tj*8 + qid*2;
                float e0 = __expf(2.f * acc[ti][tj][h*2+0]);
                float e1 = __expf(2.f * acc[ti][tj][h*2+1]);
                acc[ti][tj][h*2+0] = e0;
                acc[ti][tj][h*2+1] = e1;
                rsum += e0 + e1;
                if (diag) {
                    if (gr == gc)     dg[gr] = e0;
                    if (gr == gc + 1) dg[gr] = e1;
                }
            }
            rsum += __shfl_down_sync(0xffffffffu, rsum, 2, 4);
            rsum += __shfl_down_sync(0xffffffffu, rsum, 1, 4);
            if (qid == 0) atomicAdd(&rs[gr], rsum);
        }

    if (doCols) {
        #pragma unroll
        for (int tj = 0; tj < 4; tj++) {
            float c0 = 0.f, c1 = 0.f;
            #pragma unroll
            for (int ti = 0; ti < 4; ti++) {
                c0 += acc[ti][tj][0] + acc[ti][tj][2];
                c1 += acc[ti][tj][1] + acc[ti][tj][3];
            }
            #pragma unroll
            for (int o = 4; o <= 16; o <<= 1) {
                c0 += __shfl_xor_sync(0xffffffffu, c0, o);
                c1 += __shfl_xor_sync(0xffffffffu, c1, o);
            }
            if (grp == 0) {
                int gc = n0 + wn*32 + tj*8 + qid*2;
                atomicAdd(&cs[gc],   c0);
                atomicAdd(&cs[gc+1], c1);
            }
        }
    }
}

// ---------------- aux kernels (z-fused, unchanged from R11) ------------------
__global__ void conv_all(const float* ta, const float* tb,
                         const float* W1, const float* W2,
                         const float* W3, const float* W4)
{
    int z = blockIdx.z;
    int nblk = (z < 2) ? 2048 : 256;
    if (blockIdx.x >= (unsigned)nblk) return;
    const float* s; bf16* d;
    if (z == 0)      { s = ta; d = b_A1; }
    else if (z == 1) { s = tb; d = b_A2; }
    else if (z == 2) { s = W1; d = b_W1; }
    else if (z == 3) { s = W2; d = b_W2; }
    else if (z == 4) { s = W3; d = b_W3; }
    else             { s = W4; d = b_W4; }
    int i = blockIdx.x * blockDim.x + threadIdx.x;
    int st = nblk * 256;
    float4 v0 = ((const float4*)s)[i];
    float4 v1 = ((const float4*)s)[i + st];
    float4 v2 = ((const float4*)s)[i + 2*st];
    float4 v3 = ((const float4*)s)[i + 3*st];
    ((bf162*)d)[(i)*2+0]      = __floats2bfloat162_rn(v0.x, v0.y);
    ((bf162*)d)[(i)*2+1]      = __floats2bfloat162_rn(v0.z, v0.w);
    ((bf162*)d)[(i+st)*2+0]   = __floats2bfloat162_rn(v1.x, v1.y);
    ((bf162*)d)[(i+st)*2+1]   = __floats2bfloat162_rn(v1.z, v1.w);
    ((bf162*)d)[(i+2*st)*2+0] = __floats2bfloat162_rn(v2.x, v2.y);
    ((bf162*)d)[(i+2*st)*2+1] = __floats2bfloat162_rn(v2.z, v2.w);
    ((bf162*)d)[(i+3*st)*2+0] = __floats2bfloat162_rn(v3.x, v3.y);
    ((bf162*)d)[(i+3*st)*2+1] = __floats2bfloat162_rn(v3.z, v3.w);
}

__global__ __launch_bounds__(256) void trans_all(const float* ta, const float* tb)
{
    const float* in = blockIdx.z ? tb : ta;
    bf16* out = blockIdx.z ? b_A2c : b_A1c;
    __shared__ float t[32][33];
    const float* s = in  + (size_t)blockIdx.x * 1024;
    bf16*        d = out + (size_t)blockIdx.x * 1024;
    for (int i = threadIdx.x; i < 1024; i += 256) t[i >> 5][i & 31] = s[i];
    __syncthreads();
    for (int i = threadIdx.x; i < 1024; i += 256)
        d[i] = __float2bfloat16(t[i & 31][i >> 5]);
}

__global__ __launch_bounds__(256) void norm_all()
{
    bf16* H = (blockIdx.z == 0) ? b_H1 : (blockIdx.z == 1) ? b_H2
            : (blockIdx.z == 2) ? b_H1c : b_H2c;
    int row = blockIdx.x;
    uint2* p = (uint2*)(H + (size_t)row * DD) + threadIdx.x;
    uint2 raw = *p;
    bf162 v0 = *(bf162*)&raw.x;
    bf162 v1 = *(bf162*)&raw.y;
    float a = __bfloat162float(v0.x), b = __bfloat162float(v0.y);
    float c = __bfloat162float(v1.x), d = __bfloat162float(v1.y);
    float s = a*a + b*b + c*c + d*d;
    #pragma unroll
    for (int o = 16; o; o >>= 1) s += __shfl_xor_sync(0xffffffffu, s, o);
    __shared__ float red[8];
    int lane = threadIdx.x & 31, w = threadIdx.x >> 5;
    if (lane == 0) red[w] = s;
    __syncthreads();
    __shared__ float invn;
    if (threadIdx.x == 0) {
        float t = 0.f;
        #pragma unroll
        for (int i = 0; i < 8; i++) t += red[i];
        invn = rsqrtf(t);
    }
    __syncthreads();
    float iv = invn;
    uint2 ow;
    *(bf162*)&ow.x = __floats2bfloat162_rn(a*iv, b*iv);
    *(bf162*)&ow.y = __floats2bfloat162_rn(c*iv, d*iv);
    *p = ow;
}

__global__ void zero_stats()
{
    int i = blockIdx.x * blockDim.x + threadIdx.x;
    if (i < 2*NS) { g_r11[i] = 0.f; g_r22[i] = 0.f; g_r12[i] = 0.f; g_c12[i] = 0.f; }
    if (i < 2) g_loss[i] = 0.f;
}

__global__ void loss_all()
{
    int v = blockIdx.z;
    int i = blockIdx.x * blockDim.x + threadIdx.x;
    float val = 0.f;
    if (i < NS) {
        int k = v*NS + i;
        float ld = logf(g_d12[k]);
        float l1 = logf(g_r11[k] + g_r12[k] - g_d11[k]) - ld;
        float l2 = logf(g_r22[k] + g_c12[k] - g_d22[k]) - ld;
        val = 0.5f * (l1 + l2) * (1.0f / NS);
    }
    #pragma unroll
    for (int o = 16; o; o >>= 1) val += __shfl_down_sync(0xffffffffu, val, o);
    if ((threadIdx.x & 31) == 0) atomicAdd(&g_loss[v], val);
}

__global__ void finalize_k(const float* __restrict__ w_r1, float* __restrict__ out)
{
    float w = fminf(fmaxf(w_r1[0], 0.f), 1.f);
    out[0] = w * g_loss[0] + (1.f - w) * g_loss[1];
}

// ----------------------------------------------------------------------------
extern "C" void kernel_launch(void* const* d_in, const int* in_sizes, int n_in,
                              void* d_out, int out_size)
{
    const float* ta   = (const float*)d_in[0];
    const float* tb   = (const float*)d_in[1];
    const float* W1   = (const float*)d_in[2];
    const float* b1   = (const float*)d_in[3];
    const float* W2   = (const float*)d_in[4];
    const float* b2   = (const float*)d_in[5];
    const float* W3   = (const float*)d_in[6];
    const float* b3   = (const float*)d_in[7];
    const float* W4   = (const float*)d_in[8];
    const float* b4   = (const float*)d_in[9];
    const float* w_r1 = (const float*)d_in[10];
    float* out = (float*)d_out;

    conv_all <<<dim3(2048, 1, 6), 256>>>(ta, tb, W1, W2, W3, W4);
    trans_all<<<dim3(NS, 1, 2), 256>>>(ta, tb);
    zero_stats<<<(2*NS + 255)/256, 256>>>();
    proj1_all<<<dim3(8, 64, 4), 256>>>(b1, b3);
    proj2_all<<<dim3(8, 64, 4), 256>>>(b2, b4);
    norm_all <<<dim3(NS, 1, 4), 256>>>();
    sim_all  <<<dim3(64, 64, 6), 256>>>();
    loss_all <<<dim3(32, 1, 2), 256>>>();
    finalize_k<<<1, 1>>>(w_r1, out);
}